// round 5
// baseline (speedup 1.0000x reference)
#include <cuda_runtime.h>
#include <cstdint>

// ---------------------------------------------------------------------------
// Problem dims
// ---------------------------------------------------------------------------
#define BB   8192
#define KTOT 19000
#define SD   256
#define PDD  128
#define PP   16
#define DD   64

// GEMM tiling (R3 geometry: BM=128 x BN=256, 512 threads, warp tile 32x64)
#define BM 128
#define BN 256
#define BK 32
#define NSLICE 16
#define KSLICE 1216              // 38 tiles; last slice 760 -> 24 tiles
#define MTILES (BB / BM)         // 64
#define NUNITS (MTILES * NSLICE) // 1024
#define GRID_GEMM 148

#define A_STRIDE 36              // floats; conflict-free A frag reads
#define B_STRIDE 264             // floats; conflict-free B frag reads
#define STAGE_A_BYTES (BM * A_STRIDE * 4)        // 18432
#define STAGE_B_BYTES (BK * B_STRIDE * 4)        // 33792
#define STAGE_BYTES   (STAGE_A_BYTES + STAGE_B_BYTES)   // 52224
#define SMEM_GEMM     (3 * STAGE_BYTES)          // 156672

// pathway grouping
#define CHUNK  32
#define NCHUNK (BB / CHUNK)      // 256 (guaranteed cover; empty blocks exit)
#define SMEM_PW (SD * PDD * 4 + SD * 4 + 64)

// ---------------------------------------------------------------------------
// Device globals (no allocations allowed)
// ---------------------------------------------------------------------------
__device__ float g_hp[NSLICE][(size_t)BB * SD];   // split-K partials (bias in slice 0)
__device__ int   g_cnt[PP], g_off[PP], g_cur[PP];
__device__ int   g_ord[BB];

// ---------------------------------------------------------------------------
// helpers
// ---------------------------------------------------------------------------
__device__ __forceinline__ uint32_t smem_u32(const void* p) {
    uint32_t a;
    asm("{ .reg .u64 t; cvta.to.shared.u64 t, %1; cvt.u32.u64 %0, t; }" : "=r"(a) : "l"(p));
    return a;
}
__device__ __forceinline__ uint32_t cvt_tf32(float f) {
    uint32_t r;
    asm("cvt.rn.tf32.f32 %0, %1;" : "=r"(r) : "f"(f));
    return r;
}
__device__ __forceinline__ void cp_async16(uint32_t dst, const void* src, bool valid) {
    int sz = valid ? 16 : 0;   // sz<16 zero-fills
    asm volatile("cp.async.cg.shared.global [%0], [%1], 16, %2;\n"
                 :: "r"(dst), "l"(src), "r"(sz));
}
#define CP_COMMIT() asm volatile("cp.async.commit_group;" ::: "memory")
#define CP_WAIT1()  asm volatile("cp.async.wait_group 1;" ::: "memory")

__device__ __forceinline__ void mma_tf32(float* c, const uint32_t* a, const uint32_t* b) {
    asm volatile(
        "mma.sync.aligned.m16n8k8.row.col.f32.tf32.tf32.f32 "
        "{%0,%1,%2,%3}, {%4,%5,%6,%7}, {%8,%9}, {%0,%1,%2,%3};"
        : "+f"(c[0]), "+f"(c[1]), "+f"(c[2]), "+f"(c[3])
        : "r"(a[0]), "r"(a[1]), "r"(a[2]), "r"(a[3]), "r"(b[0]), "r"(b[1]));
}

// ---------------------------------------------------------------------------
// sort-by-pathway machinery
// ---------------------------------------------------------------------------
__global__ void zero_cnt_kernel() {
    if (threadIdx.x < PP) g_cnt[threadIdx.x] = 0;
}
__global__ void hist_kernel(const int* __restrict__ di, const int* __restrict__ d2p) {
    __shared__ int lc[PP];
    if (threadIdx.x < PP) lc[threadIdx.x] = 0;
    __syncthreads();
    int i = blockIdx.x * 256 + threadIdx.x;
    atomicAdd(&lc[d2p[di[i]]], 1);
    __syncthreads();
    if (threadIdx.x < PP) atomicAdd(&g_cnt[threadIdx.x], lc[threadIdx.x]);
}
__global__ void scan_kernel() {
    if (threadIdx.x == 0) {
        int off = 0;
        for (int p = 0; p < PP; p++) { g_off[p] = off; g_cur[p] = off; off += g_cnt[p]; }
    }
}
__global__ void scatter_kernel(const int* __restrict__ di, const int* __restrict__ d2p) {
    int i = blockIdx.x * 256 + threadIdx.x;
    int p = d2p[di[i]];
    int pos = atomicAdd(&g_cur[p], 1);
    g_ord[pos] = i;
}

// ---------------------------------------------------------------------------
// GEMM: persistent 148 CTAs, units = (m-tile, k-slice), R3 inner body.
// 512 threads = 16 warps (4m x 4n), warp tile 32x64.
// ---------------------------------------------------------------------------
#define LOAD_FRAGS(As, Bs, ks, a, b) do {                                      \
    const int _c  = (ks) * 8 + (lane & 3);                                     \
    _Pragma("unroll")                                                          \
    for (int mi = 0; mi < 2; mi++) {                                           \
        const int _r = wrow + mi * 16 + (lane >> 2);                           \
        a[mi][0] = cvt_tf32((As)[(_r    ) * A_STRIDE + _c    ]);               \
        a[mi][1] = cvt_tf32((As)[(_r + 8) * A_STRIDE + _c    ]);               \
        a[mi][2] = cvt_tf32((As)[(_r    ) * A_STRIDE + _c + 4]);               \
        a[mi][3] = cvt_tf32((As)[(_r + 8) * A_STRIDE + _c + 4]);               \
    }                                                                          \
    const int _kr = (ks) * 8 + (lane & 3);                                     \
    _Pragma("unroll")                                                          \
    for (int ni = 0; ni < 8; ni++) {                                           \
        const int _cc = wcol + ni * 8 + (lane >> 2);                           \
        b[ni][0] = cvt_tf32((Bs)[(_kr    ) * B_STRIDE + _cc]);                 \
        b[ni][1] = cvt_tf32((Bs)[(_kr + 4) * B_STRIDE + _cc]);                 \
    }                                                                          \
} while (0)

__global__ __launch_bounds__(512, 1)
void gemm_tf32_kernel(const float* __restrict__ x,
                      const float* __restrict__ W1,
                      const float* __restrict__ b1)
{
    extern __shared__ char smem[];
    const uint32_t sb = smem_u32(smem);

    const int tid  = threadIdx.x;
    const int lane = tid & 31;
    const int wid  = tid >> 5;
    const int wm   = wid & 3;
    const int wn   = wid >> 2;
    const int wrow = wm * 32;
    const int wcol = wn * 64;

    for (int u = blockIdx.x; u < NUNITS; u += GRID_GEMM) {
        const int m0     = (u >> 4) * BM;
        const int ksl    = u & 15;
        const int kstart = ksl * KSLICE;
        const int kend   = (kstart + KSLICE < KTOT) ? (kstart + KSLICE) : KTOT;
        const int ntiles = (kend - kstart + BK - 1) / BK;   // 38 or 24

        float acc[2][8][4];
#pragma unroll
        for (int mi = 0; mi < 2; mi++)
#pragma unroll
            for (int ni = 0; ni < 8; ni++)
#pragma unroll
                for (int j = 0; j < 4; j++) acc[mi][ni][j] = 0.f;

        __syncthreads();   // all warps done with previous unit's smem

        auto load_tile = [&](int kb, int stage) {
            const uint32_t ab  = sb + stage * STAGE_BYTES;
            const uint32_t bbs = ab + STAGE_A_BYTES;
#pragma unroll
            for (int i = 0; i < 2; i++) {
                int seg = tid + i * 512;            // 0..1023
                int row = seg >> 3;                 // 0..127
                int ks  = (seg & 7) << 2;           // 0..28
                int kg  = kb + ks;
                cp_async16(ab + row * (A_STRIDE * 4) + ks * 4,
                           x + (size_t)(m0 + row) * KTOT + kg, kg < kend);
            }
#pragma unroll
            for (int i = 0; i < 4; i++) {
                int seg = tid + i * 512;            // 0..2047
                int row = seg >> 6;                 // 0..31
                int ns  = (seg & 63) << 2;          // 0..252
                int kg  = kb + row;
                cp_async16(bbs + row * (B_STRIDE * 4) + ns * 4,
                           W1 + (size_t)kg * SD + ns, kg < kend);
            }
        };

        load_tile(kstart,      0); CP_COMMIT();
        load_tile(kstart + BK, 1); CP_COMMIT();

        for (int t = 0; t < ntiles; t++) {
            CP_WAIT1();
            __syncthreads();

            if (t + 2 < ntiles) load_tile(kstart + (t + 2) * BK, (t + 2) % 3);
            CP_COMMIT();

            const float* As = (const float*)(smem + (t % 3) * STAGE_BYTES);
            const float* Bs = (const float*)(smem + (t % 3) * STAGE_BYTES + STAGE_A_BYTES);

            uint32_t af[2][2][4], bf[2][8][2];
            LOAD_FRAGS(As, Bs, 0, af[0], bf[0]);
#pragma unroll
            for (int ks = 0; ks < 4; ks++) {
                const int cur = ks & 1;
                if (ks < 3) LOAD_FRAGS(As, Bs, ks + 1, af[cur ^ 1], bf[cur ^ 1]);
#pragma unroll
                for (int mi = 0; mi < 2; mi++)
#pragma unroll
                    for (int ni = 0; ni < 8; ni++)
                        mma_tf32(acc[mi][ni], af[cur][mi], bf[cur][ni]);
            }
            // no trailing syncthreads: top-of-next-iter barrier orders
            // compute(t) before any load into this slot (reused at t+3)
        }

        // epilogue: partial h for this k-slice (bias folded into slice 0)
        float* op = g_hp[ksl];
#pragma unroll
        for (int mi = 0; mi < 2; mi++) {
            int r0 = m0 + wrow + mi * 16 + (lane >> 2);
#pragma unroll
            for (int ni = 0; ni < 8; ni++) {
                int c = wcol + ni * 8 + (lane & 3) * 2;
                float bx = 0.f, by = 0.f;
                if (ksl == 0) { bx = __ldg(&b1[c]); by = __ldg(&b1[c + 1]); }
                float2 v0 = make_float2(acc[mi][ni][0] + bx, acc[mi][ni][1] + by);
                float2 v1 = make_float2(acc[mi][ni][2] + bx, acc[mi][ni][3] + by);
                *(float2*)(op + (size_t)r0 * SD + c)       = v0;
                *(float2*)(op + (size_t)(r0 + 8) * SD + c) = v1;
            }
        }
    }
}

// ---------------------------------------------------------------------------
// Grouped pathway kernel: block = (pathway p, 32-sample chunk).
// Wp[p] cached in smem (128 KB). Thread t owns output column t.
// ---------------------------------------------------------------------------
__global__ __launch_bounds__(128)
void pathway_grouped_kernel(const float* __restrict__ Wp,
                            const float* __restrict__ bp,
                            const float* __restrict__ Wd,
                            const float* __restrict__ bd,
                            const int*   __restrict__ di,
                            float*       __restrict__ out)
{
    extern __shared__ float sm[];
    float* wps = sm;                 // [SD][PDD]
    float* hs  = sm + SD * PDD;      // [SD]
    float* red = hs + SD;            // [4]

    const int p    = blockIdx.x;
    const int base = blockIdx.y * CHUNK;
    const int cnt  = g_cnt[p];
    if (base >= cnt) return;

    const int t = threadIdx.x;

    const float4* wsrc = (const float4*)(Wp + (size_t)p * SD * PDD);
    float4* wdst = (float4*)wps;
#pragma unroll
    for (int i = 0; i < 64; i++) wdst[t + i * 128] = wsrc[t + i * 128];

    const float bpv   = bp[p * PDD + t];
    const int   nloc  = min(CHUNK, cnt - base);
    const int   obase = g_off[p] + base;
    __syncthreads();

    for (int j = 0; j < nloc; j++) {
        const int sample = g_ord[obase + j];

        float h0 = 0.f, h1 = 0.f;
        const size_t i0 = (size_t)sample * SD + t;
#pragma unroll
        for (int q = 0; q < NSLICE; q++) {
            h0 += g_hp[q][i0];
            h1 += g_hp[q][i0 + 128];
        }
        hs[t]       = fmaxf(h0, 0.f);
        hs[t + 128] = fmaxf(h1, 0.f);
        __syncthreads();

        float acc = bpv;
#pragma unroll 8
        for (int s = 0; s < SD; s++)
            acc = fmaf(hs[s], wps[s * PDD + t], acc);
        acc = fmaxf(acc, 0.f);

        const int drug = di[sample];
        float v = acc * Wd[drug * PDD + t];
#pragma unroll
        for (int off = 16; off > 0; off >>= 1)
            v += __shfl_xor_sync(0xffffffffu, v, off);
        if ((t & 31) == 0) red[t >> 5] = v;
        __syncthreads();
        if (t == 0)
            out[sample] = red[0] + red[1] + red[2] + red[3] + bd[drug];
        __syncthreads();
    }
}

// ---------------------------------------------------------------------------
// Launch. Inputs: x, drug_indices, W1, b1, Wp, bp, Wd, bd, drug_to_pw
// ---------------------------------------------------------------------------
extern "C" void kernel_launch(void* const* d_in, const int* in_sizes, int n_in,
                              void* d_out, int out_size)
{
    const float* x            = (const float*)d_in[0];
    const int*   drug_indices = (const int*)  d_in[1];
    const float* W1           = (const float*)d_in[2];
    const float* b1           = (const float*)d_in[3];
    const float* Wp           = (const float*)d_in[4];
    const float* bp           = (const float*)d_in[5];
    const float* Wd           = (const float*)d_in[6];
    const float* bd           = (const float*)d_in[7];
    const int*   drug_to_pw   = (const int*)  d_in[8];
    float*       out          = (float*)d_out;

    static int attr_set = 0;
    if (!attr_set) {
        cudaFuncSetAttribute(gemm_tf32_kernel,
                             cudaFuncAttributeMaxDynamicSharedMemorySize, SMEM_GEMM);
        cudaFuncSetAttribute(pathway_grouped_kernel,
                             cudaFuncAttributeMaxDynamicSharedMemorySize, SMEM_PW);
        attr_set = 1;
    }

    // sort-by-pathway prep (tiny; runs before pathway kernel needs it)
    zero_cnt_kernel<<<1, 32>>>();
    hist_kernel<<<BB / 256, 256>>>(drug_indices, drug_to_pw);
    scan_kernel<<<1, 32>>>();
    scatter_kernel<<<BB / 256, 256>>>(drug_indices, drug_to_pw);

    // persistent GEMM
    gemm_tf32_kernel<<<GRID_GEMM, 512, SMEM_GEMM>>>(x, W1, b1);

    // grouped pathway + drug head
    pathway_grouped_kernel<<<dim3(PP, NCHUNK), 128, SMEM_PW>>>(
        Wp, bp, Wd, bd, drug_indices, out);
}

// round 7
// speedup vs baseline: 1.9236x; 1.9236x over previous
#include <cuda_runtime.h>
#include <cuda_fp16.h>
#include <cstdint>

// ---------------------------------------------------------------------------
// Problem dims
// ---------------------------------------------------------------------------
#define BB   8192
#define KTOT 19000
#define SD   256
#define PDD  128
#define PP   16
#define DD   64

// GEMM tiling: BM=128 x BN=256, BK=32, 512 threads (16 warps 4m x 4n),
// warp tile 32x64, split-K=2, grid (64, 2).
#define BM 128
#define BK 32
#define KHALF 9504               // 297 tiles of 32 (half 1 guarded at 19000)
#define NTILES 297
#define STAGES 4

#define A_ST 40                  // A smem stride (floats): conflict-free LDS.64
#define B_STH 40                 // B smem stride (halves): conflict-free ldmatrix
#define STAGE_A_BYTES (BM * A_ST * 4)       // 20480
#define STAGE_B_BYTES (SD * B_STH * 2)      // 20480
#define STAGE_BYTES   (STAGE_A_BYTES + STAGE_B_BYTES)   // 40960
#define SMEM_GEMM     (STAGES * STAGE_BYTES)            // 163840

// ---------------------------------------------------------------------------
// Device globals (no allocations allowed)
// ---------------------------------------------------------------------------
__device__ __half g_w1t[(size_t)SD * KTOT];  // W1 transposed -> fp16, [n][k]
__device__ float  g_h_a[(size_t)BB * SD];    // split 0 partial (+bias)
__device__ float  g_h_b[(size_t)BB * SD];    // split 1 partial

// ---------------------------------------------------------------------------
// helpers
// ---------------------------------------------------------------------------
__device__ __forceinline__ uint32_t smem_u32(const void* p) {
    uint32_t a;
    asm("{ .reg .u64 t; cvta.to.shared.u64 t, %1; cvt.u32.u64 %0, t; }" : "=r"(a) : "l"(p));
    return a;
}
__device__ __forceinline__ uint32_t pack_f16x2(float hi, float lo) {
    uint32_t r;
    asm("cvt.rn.f16x2.f32 %0, %1, %2;" : "=r"(r) : "f"(hi), "f"(lo));
    return r;
}
__device__ __forceinline__ void cp_async16(uint32_t dst, const void* src, bool valid) {
    int sz = valid ? 16 : 0;   // sz<16 zero-fills
    asm volatile("cp.async.cg.shared.global [%0], [%1], 16, %2;\n"
                 :: "r"(dst), "l"(src), "r"(sz));
}
#define CP_COMMIT() asm volatile("cp.async.commit_group;" ::: "memory")
#define CP_WAIT2()  asm volatile("cp.async.wait_group 2;" ::: "memory")

__device__ __forceinline__ void mma_f16(float* c, const uint32_t* a, const uint32_t* b) {
    asm volatile(
        "mma.sync.aligned.m16n8k16.row.col.f32.f16.f16.f32 "
        "{%0,%1,%2,%3}, {%4,%5,%6,%7}, {%8,%9}, {%0,%1,%2,%3};"
        : "+f"(c[0]), "+f"(c[1]), "+f"(c[2]), "+f"(c[3])
        : "r"(a[0]), "r"(a[1]), "r"(a[2]), "r"(a[3]), "r"(b[0]), "r"(b[1]));
}
__device__ __forceinline__ void ldmatrix_x4(uint32_t* r, uint32_t addr) {
    asm volatile("ldmatrix.sync.aligned.m8n8.x4.shared.b16 {%0,%1,%2,%3}, [%4];"
                 : "=r"(r[0]), "=r"(r[1]), "=r"(r[2]), "=r"(r[3]) : "r"(addr));
}

// ---------------------------------------------------------------------------
// Kernel 0: W1 [K][N] f32 -> g_w1t [N][K] fp16 (tiled transpose)
// ---------------------------------------------------------------------------
__global__ void transpose_w1_kernel(const float* __restrict__ W1) {
    __shared__ __half tile[32][33];
    const int k0 = blockIdx.x * 32;
    const int n0 = blockIdx.y * 32;
    const int tx = threadIdx.x;   // 0..31
    const int ty = threadIdx.y;   // 0..7
#pragma unroll
    for (int j = 0; j < 4; j++) {
        int k = k0 + ty + j * 8;
        float v = (k < KTOT) ? W1[(size_t)k * SD + n0 + tx] : 0.f;
        tile[ty + j * 8][tx] = __float2half_rn(v);
    }
    __syncthreads();
    int k = k0 + tx;
    if (k < KTOT) {
#pragma unroll
        for (int j = 0; j < 4; j++) {
            int n = n0 + ty + j * 8;
            g_w1t[(size_t)n * KTOT + k] = tile[tx][ty + j * 8];
        }
    }
}

// ---------------------------------------------------------------------------
// GEMM: h_partial = x @ W1 via fp16 m16n8k16 mma.sync, fp32 accumulate.
// A (x) kept fp32 in smem, converted in registers; B (W1) fp16 via ldmatrix.
// ---------------------------------------------------------------------------
#define LOAD_FRAGS_F16(As, bsb, s, a, b) do {                                  \
    const int _q2 = (lane & 3) * 2;                                            \
    _Pragma("unroll")                                                          \
    for (int mi = 0; mi < 2; mi++) {                                           \
        const int _base = (wrow + mi * 16 + (lane >> 2)) * A_ST + (s) * 16 + _q2; \
        float2 _v0 = *(const float2*)&(As)[_base];                             \
        float2 _v1 = *(const float2*)&(As)[_base + 8 * A_ST];                  \
        float2 _v2 = *(const float2*)&(As)[_base + 8];                         \
        float2 _v3 = *(const float2*)&(As)[_base + 8 * A_ST + 8];              \
        a[mi][0] = pack_f16x2(_v0.y, _v0.x);                                   \
        a[mi][1] = pack_f16x2(_v1.y, _v1.x);                                   \
        a[mi][2] = pack_f16x2(_v2.y, _v2.x);                                   \
        a[mi][3] = pack_f16x2(_v3.y, _v3.x);                                   \
    }                                                                          \
    const int _g  = lane >> 3;                                                 \
    const int _rr = lane & 7;                                                  \
    const int _nr = _rr + ((_g >> 1) << 3);                                    \
    const int _kc = (s) * 16 + ((_g & 1) << 3);                                \
    _Pragma("unroll")                                                          \
    for (int j = 0; j < 4; j++) {                                              \
        uint32_t _addr = (bsb) + ((wcol + j * 16 + _nr) * B_STH + _kc) * 2;    \
        uint32_t _r[4];                                                        \
        ldmatrix_x4(_r, _addr);                                                \
        b[2*j  ][0] = _r[0]; b[2*j  ][1] = _r[1];                              \
        b[2*j+1][0] = _r[2]; b[2*j+1][1] = _r[3];                              \
    }                                                                          \
} while (0)

__global__ __launch_bounds__(512, 1)
void gemm_f16_kernel(const float* __restrict__ x, const float* __restrict__ b1)
{
    extern __shared__ char smem[];
    const uint32_t sb = smem_u32(smem);

    const int tid  = threadIdx.x;
    const int lane = tid & 31;
    const int wid  = tid >> 5;
    const int wrow = (wid & 3) * 32;
    const int wcol = (wid >> 2) * 64;
    const int m0   = blockIdx.x * BM;
    const int ky   = blockIdx.y;
    const int kstart = ky * KHALF;
    const int kend   = (ky == 0) ? KHALF : KTOT;

    float acc[2][8][4];
#pragma unroll
    for (int mi = 0; mi < 2; mi++)
#pragma unroll
        for (int ni = 0; ni < 8; ni++)
#pragma unroll
            for (int j = 0; j < 4; j++) acc[mi][ni][j] = 0.f;

    auto load_tile = [&](int kb, int stage) {
        const uint32_t ab  = sb + stage * STAGE_BYTES;
        const uint32_t bbs = ab + STAGE_A_BYTES;
        // A: 128 rows x 32 fp32 = 1024 16B chunks
#pragma unroll
        for (int i = 0; i < 2; i++) {
            int c   = tid + i * 512;
            int row = c >> 3;
            int ko  = (c & 7) << 2;
            int kg  = kb + ko;
            cp_async16(ab + row * (A_ST * 4) + ko * 4,
                       x + (size_t)(m0 + row) * KTOT + kg, kg < kend);
        }
        // B: 256 rows x 32 fp16 = 1024 16B chunks
#pragma unroll
        for (int i = 0; i < 2; i++) {
            int c   = tid + i * 512;
            int row = c >> 2;
            int ko  = (c & 3) << 3;
            int kg  = kb + ko;
            cp_async16(bbs + (row * B_STH + ko) * 2,
                       g_w1t + (size_t)row * KTOT + kg, kg < kend);
        }
    };

#pragma unroll
    for (int s = 0; s < 3; s++) { load_tile(kstart + s * BK, s); CP_COMMIT(); }

    for (int t = 0; t < NTILES; t++) {
        CP_WAIT2();
        __syncthreads();

        if (t + 3 < NTILES) load_tile(kstart + (t + 3) * BK, (t + 3) & 3);
        CP_COMMIT();

        const float* As = (const float*)(smem + (t & 3) * STAGE_BYTES);
        const uint32_t bsb = sb + (t & 3) * STAGE_BYTES + STAGE_A_BYTES;

        uint32_t af[2][2][4], bf[2][8][2];
        LOAD_FRAGS_F16(As, bsb, 0, af[0], bf[0]);
#pragma unroll
        for (int s = 0; s < 2; s++) {
            if (s == 0) LOAD_FRAGS_F16(As, bsb, 1, af[1], bf[1]);
#pragma unroll
            for (int mi = 0; mi < 2; mi++)
#pragma unroll
                for (int ni = 0; ni < 8; ni++)
                    mma_f16(acc[mi][ni], af[s][mi], bf[s][ni]);
        }
        // top-of-next-iter barrier orders compute(t) before reuse at t+4
    }

    // epilogue: partial h (bias folded into split 0)
    float* op = (ky == 0) ? g_h_a : g_h_b;
#pragma unroll
    for (int mi = 0; mi < 2; mi++) {
        int r0 = m0 + wrow + mi * 16 + (lane >> 2);
#pragma unroll
        for (int ni = 0; ni < 8; ni++) {
            int c = wcol + ni * 8 + (lane & 3) * 2;
            float bx = 0.f, by = 0.f;
            if (ky == 0) { bx = __ldg(&b1[c]); by = __ldg(&b1[c + 1]); }
            float2 v0 = make_float2(acc[mi][ni][0] + bx, acc[mi][ni][1] + by);
            float2 v1 = make_float2(acc[mi][ni][2] + bx, acc[mi][ni][3] + by);
            *(float2*)(op + (size_t)r0 * SD + c)       = v0;
            *(float2*)(op + (size_t)(r0 + 8) * SD + c) = v1;
        }
    }
}

// ---------------------------------------------------------------------------
// Kernel 2: per-sample pathway expert + drug head (R3 proven version).
// ---------------------------------------------------------------------------
__global__ __launch_bounds__(128)
void pathway_drug_kernel(const float* __restrict__ Wp,
                         const float* __restrict__ bp,
                         const float* __restrict__ Wd,
                         const float* __restrict__ bd,
                         const int*   __restrict__ drug_indices,
                         const int*   __restrict__ drug_to_pw,
                         float*       __restrict__ out)
{
    const int b   = blockIdx.x;
    const int tid = threadIdx.x;

    __shared__ float hs[SD];
    __shared__ float red[4];

    const int drug = drug_indices[b];
    const int p    = drug_to_pw[drug];

    {
        size_t i0 = (size_t)b * SD + tid;
        hs[tid]       = fmaxf(g_h_a[i0]       + g_h_b[i0],       0.f);
        hs[tid + 128] = fmaxf(g_h_a[i0 + 128] + g_h_b[i0 + 128], 0.f);
    }
    __syncthreads();

    const float* wcol = Wp + (size_t)p * SD * PDD + tid;
    float acc = 0.f;
#pragma unroll 8
    for (int s = 0; s < SD; s++)
        acc = fmaf(hs[s], wcol[(size_t)s * PDD], acc);

    acc += bp[p * PDD + tid];
    acc = fmaxf(acc, 0.f);

    float v = acc * Wd[drug * PDD + tid];
#pragma unroll
    for (int off = 16; off > 0; off >>= 1)
        v += __shfl_xor_sync(0xffffffffu, v, off);
    if ((tid & 31) == 0) red[tid >> 5] = v;
    __syncthreads();
    if (tid == 0)
        out[b] = red[0] + red[1] + red[2] + red[3] + bd[drug];
}

// ---------------------------------------------------------------------------
// Launch. Inputs: x, drug_indices, W1, b1, Wp, bp, Wd, bd, drug_to_pw
// ---------------------------------------------------------------------------
extern "C" void kernel_launch(void* const* d_in, const int* in_sizes, int n_in,
                              void* d_out, int out_size)
{
    const float* x            = (const float*)d_in[0];
    const int*   drug_indices = (const int*)  d_in[1];
    const float* W1           = (const float*)d_in[2];
    const float* b1           = (const float*)d_in[3];
    const float* Wp           = (const float*)d_in[4];
    const float* bp           = (const float*)d_in[5];
    const float* Wd           = (const float*)d_in[6];
    const float* bd           = (const float*)d_in[7];
    const int*   drug_to_pw   = (const int*)  d_in[8];
    float*       out          = (float*)d_out;

    static int attr_set = 0;
    if (!attr_set) {
        cudaFuncSetAttribute(gemm_f16_kernel,
                             cudaFuncAttributeMaxDynamicSharedMemorySize, SMEM_GEMM);
        attr_set = 1;
    }

    dim3 tgrid((KTOT + 31) / 32, SD / 32);
    transpose_w1_kernel<<<tgrid, dim3(32, 8)>>>(W1);

    dim3 ggrid(BB / BM, 2);
    gemm_f16_kernel<<<ggrid, 512, SMEM_GEMM>>>(x, b1);

    pathway_drug_kernel<<<BB, 128>>>(Wp, bp, Wd, bd, drug_indices, drug_to_pw, out);
}